// round 14
// baseline (speedup 1.0000x reference)
#include <cuda_runtime.h>
#include <math.h>

#define N_NODES 50000
#define N_EDGES 100000
#define FN 22
#define FE 4
#define H 64
#define BN_EPS 1e-5
#define EB 8            // edges per block-batch

typedef unsigned long long u64;

// ---------------- packed f32x2 helpers ----------------
__device__ __forceinline__ u64 pack2(float lo, float hi) {
    u64 r; asm("mov.b64 %0, {%1, %2};" : "=l"(r) : "f"(lo), "f"(hi)); return r;
}
__device__ __forceinline__ void unpack2(u64 v, float& lo, float& hi) {
    asm("mov.b64 {%0, %1}, %2;" : "=f"(lo), "=f"(hi) : "l"(v));
}
__device__ __forceinline__ u64 fma2(u64 a, u64 b, u64 c) {
    u64 d; asm("fma.rn.f32x2 %0, %1, %2, %3;" : "=l"(d) : "l"(a), "l"(b), "l"(c)); return d;
}
__device__ __forceinline__ u64 add2(u64 a, u64 b) {
    u64 d; asm("add.rn.f32x2 %0, %1, %2;" : "=l"(d) : "l"(a), "l"(b)); return d;
}
__device__ __forceinline__ u64 relu2(u64 v) {
    float a, b; unpack2(v, a, b);
    return pack2(fmaxf(a, 0.f), fmaxf(b, 0.f));
}

// ---------------- scratch (static device globals) ----------------
__device__ float d_agg1[N_NODES * H];
__device__ float d_h1  [N_NODES * H];
__device__ float d_agg2[N_NODES * H];
__device__ u64   d_We1p[24 * 32 * 4];   // [i<24][cp<32][f<4] packed col-pairs (zero-padded i>=22)
__device__ u64   d_be1p[24 * 32];
__device__ u64   d_We2p[64 * 32 * 4];
__device__ u64   d_be2p[64 * 32];
__device__ u64   d_root1p[FN * 32];     // [i<22][cp] packed col-pairs of root1
__device__ u64   d_root2p[64 * 32];     // [i][cp]
__device__ float d_stats[4 * H];        // sum1, sq1, sum2, sq2

// ---------------- dummy (positions ncu capture on the edge2 pre-pass) ----------------
__global__ void k_dummy() {}

// ---------------- prep: pack weights, zero stats ----------------
__global__ void k_prep(const float* __restrict__ We1, const float* __restrict__ be1,
                       const float* __restrict__ We2, const float* __restrict__ be2,
                       const float* __restrict__ root1, const float* __restrict__ root2) {
    int j = blockIdx.x * blockDim.x + threadIdx.x;
    if (j < 64 * 32 * 4) {
        int f = j & 3, cp = (j >> 2) & 31, i = j >> 7;
        d_We2p[j] = pack2(We2[f * 4096 + i * 64 + 2 * cp], We2[f * 4096 + i * 64 + 2 * cp + 1]);
    }
    if (j < 24 * 32 * 4) {
        int f = j & 3, cp = (j >> 2) & 31, i = j >> 7;
        d_We1p[j] = (i < FN) ? pack2(We1[f * 1408 + i * 64 + 2 * cp],
                                     We1[f * 1408 + i * 64 + 2 * cp + 1]) : 0ULL;
    }
    if (j < 64 * 32) {
        int cp = j & 31, i = j >> 5;
        d_be2p[j]   = pack2(be2[i * 64 + 2 * cp],   be2[i * 64 + 2 * cp + 1]);
        d_root2p[j] = pack2(root2[i * 64 + 2 * cp], root2[i * 64 + 2 * cp + 1]);
    }
    if (j < 24 * 32) {
        int cp = j & 31, i = j >> 5;
        d_be1p[j] = (i < FN) ? pack2(be1[i * 64 + 2 * cp], be1[i * 64 + 2 * cp + 1]) : 0ULL;
    }
    if (j < FN * 32) {
        int cp = j & 31, i = j >> 5;
        d_root1p[j] = pack2(root1[i * 64 + 2 * cp], root1[i * 64 + 2 * cp + 1]);
    }
    if (j < 4 * H) d_stats[j] = 0.f;
}

// ---------------- agg1 = x @ root1 + b1 (shared-staged, packed) ----------------
__global__ __launch_bounds__(256, 4)
void k_init_agg1(const float* __restrict__ x, const float* __restrict__ b1) {
    __shared__ u64   sh_r1[FN * 32];
    __shared__ float sh_x[16 * FN];
    const int tid = threadIdx.x;
    const int nb = blockIdx.x * 16;

    for (int t = tid; t < FN * 32; t += 256) sh_r1[t] = d_root1p[t];
    for (int t = tid; t < 16 * FN; t += 256) sh_x[t] = __ldg(&x[nb * FN + t]);
    __syncthreads();

    const int cp  = tid & 31;
    const int nl0 = (tid >> 5) * 2, nl1 = nl0 + 1;
    u64 bias = pack2(__ldg(&b1[2 * cp]), __ldg(&b1[2 * cp + 1]));
    u64 acc0 = bias, acc1 = bias;
#pragma unroll
    for (int i = 0; i < FN; i++) {
        u64 w = sh_r1[i * 32 + cp];
        float h0 = sh_x[nl0 * FN + i], h1 = sh_x[nl1 * FN + i];
        acc0 = fma2(pack2(h0, h0), w, acc0);
        acc1 = fma2(pack2(h1, h1), w, acc1);
    }
    float a, b;
    unpack2(acc0, a, b); ((float2*)&d_agg1[(nb + nl0) * H])[cp] = make_float2(a, b);
    unpack2(acc1, a, b); ((float2*)&d_agg1[(nb + nl1) * H])[cp] = make_float2(a, b);
}

// ---------------- layer-1 edge kernel: STS partials + warp-per-edge reduce (R11 best) ----
__global__ __launch_bounds__(256, 3)
void k_edge1(const float* __restrict__ x, const float4* __restrict__ ea4,
             const int* __restrict__ eidx) {
    const int tid = threadIdx.x;
    const int cp = tid >> 3;
    const int ig = tid & 7;
    const int wid = tid >> 5, lane = tid & 31;
    u64 W[3][4]; u64 B[3];
#pragma unroll
    for (int ii = 0; ii < 3; ii++) {
        int i = ig * 3 + ii;
#pragma unroll
        for (int f = 0; f < 4; f++) W[ii][f] = d_We1p[(i * 32 + cp) * 4 + f];
        B[ii] = d_be1p[i * 32 + cp];
    }
    __shared__ float  sh_x[2][EB][24];
    __shared__ float4 sh_ea[2][EB];
    __shared__ int    sh_dst[2][EB];
    __shared__ u64    sh_part[EB * 264];   // [k][ig] pitch-33 [cp]

    auto load = [&](int b, int buf) {
        int e = b + wid;
        if (e < N_EDGES) {
            int src = __ldg(&eidx[e]);
            if (lane < 24)
                sh_x[buf][wid][lane] = (lane < FN) ? __ldg(&x[src * FN + lane]) : 0.f;
            if (lane == 0) {
                sh_ea[buf][wid]  = __ldg(&ea4[e]);
                sh_dst[buf][wid] = __ldg(&eidx[N_EDGES + e]);
            }
        }
    };

    const int step = gridDim.x * EB;
    int base = blockIdx.x * EB;
    load(base, 0);
    int buf = 0;
    for (int b = base; b < N_EDGES; b += step) {
        __syncthreads();                       // prefetch visible AND prev reduce done
        if (b + step < N_EDGES) load(b + step, buf ^ 1);
        int emax = min(EB, N_EDGES - b);
        for (int k = 0; k < emax; k++) {
            float4 a = sh_ea[buf][k];
            u64 ax = pack2(a.x, a.x), ay = pack2(a.y, a.y);
            u64 az = pack2(a.z, a.z), aw = pack2(a.w, a.w);
            u64 acc = 0ULL;
#pragma unroll
            for (int ii = 0; ii < 3; ii++) {
                u64 w = fma2(ax, W[ii][0], B[ii]);
                w = fma2(ay, W[ii][1], w);
                w = fma2(az, W[ii][2], w);
                w = fma2(aw, W[ii][3], w);
                w = relu2(w);
                float h = sh_x[buf][k][ig * 3 + ii];
                acc = fma2(pack2(h, h), w, acc);
            }
            sh_part[k * 264 + ig * 33 + cp] = acc;   // STS.64, no tail
        }
        __syncthreads();
        if (wid < emax) {                      // warp wid reduces edge wid
            const u64* p = &sh_part[wid * 264 + lane];
            u64 s = add2(add2(add2(p[0],   p[33]),  add2(p[66],  p[99])),
                         add2(add2(p[132], p[165]), add2(p[198], p[231])));
            float s0, s1; unpack2(s, s0, s1);
            int dst = sh_dst[buf][wid];
            atomicAdd(&d_agg1[dst * H + 2 * lane],     s0);
            atomicAdd(&d_agg1[dst * H + 2 * lane + 1], s1);
        }
        buf ^= 1;
    }
}

// ---------------- BN stats (fp32, float4 loads, 512 threads) ----------------
__global__ __launch_bounds__(512)
void k_stats(int layer) {
    const float4* __restrict__ src = (const float4*)(layer ? d_agg2 : d_agg1);
    int og = threadIdx.x & 15;
    int r  = threadIdx.x >> 4;
    float4 s  = make_float4(0.f, 0.f, 0.f, 0.f);
    float4 ss = make_float4(0.f, 0.f, 0.f, 0.f);
#pragma unroll 4
    for (int n = blockIdx.x * 32 + r; n < N_NODES; n += gridDim.x * 32) {
        float4 v = src[n * 16 + og];
        s.x += v.x; s.y += v.y; s.z += v.z; s.w += v.w;
        ss.x += v.x * v.x; ss.y += v.y * v.y; ss.z += v.z * v.z; ss.w += v.w * v.w;
    }
    __shared__ float4 shs[512], shss[512];
    shs[threadIdx.x] = s; shss[threadIdx.x] = ss;
    __syncthreads();
    for (int str = 256; str >= 16; str >>= 1) {
        if (threadIdx.x < str) {
            float4 a = shs[threadIdx.x], b = shs[threadIdx.x + str];
            shs[threadIdx.x] = make_float4(a.x + b.x, a.y + b.y, a.z + b.z, a.w + b.w);
            a = shss[threadIdx.x]; b = shss[threadIdx.x + str];
            shss[threadIdx.x] = make_float4(a.x + b.x, a.y + b.y, a.z + b.z, a.w + b.w);
        }
        __syncthreads();
    }
    if (threadIdx.x < 16) {
        float4 a = shs[threadIdx.x], b = shss[threadIdx.x];
        float* ps = &d_stats[layer * 2 * H + threadIdx.x * 4];
        float* pq = &d_stats[layer * 2 * H + H + threadIdx.x * 4];
        atomicAdd(&ps[0], a.x); atomicAdd(&ps[1], a.y); atomicAdd(&ps[2], a.z); atomicAdd(&ps[3], a.w);
        atomicAdd(&pq[0], b.x); atomicAdd(&pq[1], b.y); atomicAdd(&pq[2], b.z); atomicAdd(&pq[3], b.w);
    }
}

// ---------------- fused: BN1 finalize+apply + ReLU -> h1 ; agg2 = h1 @ root2 + b2 ----------------
__global__ __launch_bounds__(256, 4)
void k_init_agg2(const float* __restrict__ b2, const float* __restrict__ g,
                 const float* __restrict__ beta) {
    __shared__ u64   sh_r2[64 * 32];
    __shared__ float sh_h[16][H];
    __shared__ float s_sc[H], s_sf[H];
    const int tid = threadIdx.x;
    const int wid = tid >> 5, lane = tid & 31;
    const int nb = blockIdx.x * 16;

    if (tid < H) {
        double sm  = (double)d_stats[tid];
        double sq  = (double)d_stats[H + tid];
        double mu  = sm / (double)N_NODES;
        double var = sq / (double)N_NODES - mu * mu;
        float rs = (float)(1.0 / sqrt(var + BN_EPS));
        float sc = __ldg(&g[tid]) * rs;
        s_sc[tid] = sc;
        s_sf[tid] = __ldg(&beta[tid]) - (float)mu * sc;
    }
    for (int t = tid; t < 64 * 32; t += 256) sh_r2[t] = d_root2p[t];
    __syncthreads();

    float2 sc = ((const float2*)s_sc)[lane];
    float2 sf = ((const float2*)s_sf)[lane];
#pragma unroll
    for (int rep = 0; rep < 2; rep++) {
        int nl = wid + rep * 8;
        int node = nb + nl;
        float2 v = ((const float2*)&d_agg1[node * H])[lane];
        v.x = fmaxf(fmaf(v.x, sc.x, sf.x), 0.f);
        v.y = fmaxf(fmaf(v.y, sc.y, sf.y), 0.f);
        ((float2*)&sh_h[nl][0])[lane] = v;
        ((float2*)&d_h1[node * H])[lane] = v;
    }
    __syncthreads();

    const int cp = tid & 31;
    const int nl0 = (tid >> 5) * 2, nl1 = nl0 + 1;
    u64 bias = pack2(__ldg(&b2[2 * cp]), __ldg(&b2[2 * cp + 1]));
    u64 acc0 = bias, acc1 = bias;
#pragma unroll
    for (int i = 0; i < H; i++) {
        u64 w2 = sh_r2[i * 32 + cp];
        float h0 = sh_h[nl0][i], h1 = sh_h[nl1][i];
        acc0 = fma2(pack2(h0, h0), w2, acc0);
        acc1 = fma2(pack2(h1, h1), w2, acc1);
    }
    float a, b;
    unpack2(acc0, a, b); ((float2*)&d_agg2[(nb + nl0) * H])[cp] = make_float2(a, b);
    unpack2(acc1, a, b); ((float2*)&d_agg2[(nb + nl1) * H])[cp] = make_float2(a, b);
}

// ---------------- layer-2 edge kernel: i-split across blockIdx.y, 40 weight regs ----------
// block (x, iy): iy selects input half [iy*32, iy*32+32); partial sums combine via atomics.
// thread: cp = tid>>3 (col pair), ig = tid&7 covers 4 inputs iy*32 + ig*4 + ii.
__global__ __launch_bounds__(256, 3)
void k_edge2(const float4* __restrict__ ea4, const int* __restrict__ eidx, int n_edges) {
    const int tid = threadIdx.x;
    const int cp = tid >> 3;
    const int ig = tid & 7;
    const int wid = tid >> 5, lane = tid & 31;
    const int ibase = blockIdx.y * 32 + ig * 4;
    u64 W[4][4]; u64 B[4];
#pragma unroll
    for (int ii = 0; ii < 4; ii++) {
        int i = ibase + ii;
#pragma unroll
        for (int f = 0; f < 4; f++) W[ii][f] = d_We2p[(i * 32 + cp) * 4 + f];
        B[ii] = d_be2p[i * 32 + cp];
    }
    __shared__ float  sh_h[2][EB][32];     // only this block's input half
    __shared__ float4 sh_ea[2][EB];
    __shared__ int    sh_dst[2][EB];
    __shared__ u64    sh_part[EB * 264];   // [k][ig] pitch-33 [cp]

    auto load = [&](int b, int buf) {
        int e = b + wid;
        if (e < n_edges) {
            int src = __ldg(&eidx[e]);
            if (lane == 0) {
                sh_ea[buf][wid]  = __ldg(&ea4[e]);
                sh_dst[buf][wid] = __ldg(&eidx[N_EDGES + e]);
            }
            // 32 floats of this half: one float per lane
            sh_h[buf][wid][lane] = __ldg(&d_h1[src * H + blockIdx.y * 32 + lane]);
        }
    };

    const int step = gridDim.x * EB;
    int base = blockIdx.x * EB;
    load(base, 0);
    int buf = 0;
    for (int b = base; b < n_edges; b += step) {
        __syncthreads();                       // prefetch visible AND prev reduce done
        if (b + step < n_edges) load(b + step, buf ^ 1);
        int emax = min(EB, n_edges - b);
        for (int k = 0; k < emax; k++) {
            float4 a = sh_ea[buf][k];
            u64 ax = pack2(a.x, a.x), ay = pack2(a.y, a.y);
            u64 az = pack2(a.z, a.z), aw = pack2(a.w, a.w);
            u64 acc = 0ULL;
#pragma unroll
            for (int ii = 0; ii < 4; ii++) {
                u64 w = fma2(ax, W[ii][0], B[ii]);
                w = fma2(ay, W[ii][1], w);
                w = fma2(az, W[ii][2], w);
                w = fma2(aw, W[ii][3], w);
                w = relu2(w);
                float h = sh_h[buf][k][ig * 4 + ii];
                acc = fma2(pack2(h, h), w, acc);
            }
            sh_part[k * 264 + ig * 33 + cp] = acc;
        }
        __syncthreads();
        if (wid < emax) {
            const u64* p = &sh_part[wid * 264 + lane];
            u64 s = add2(add2(add2(p[0],   p[33]),  add2(p[66],  p[99])),
                         add2(add2(p[132], p[165]), add2(p[198], p[231])));
            float s0, s1; unpack2(s, s0, s1);
            int dst = sh_dst[buf][wid];
            atomicAdd(&d_agg2[dst * H + 2 * lane],     s0);
            atomicAdd(&d_agg2[dst * H + 2 * lane + 1], s1);
        }
        buf ^= 1;
    }
}

// ---------------- BN2 finalize+apply + ReLU + FC + sigmoid ----------------
__global__ void k_final(const float* __restrict__ g, const float* __restrict__ beta,
                        const float* __restrict__ Wfc, const float* __restrict__ bfc,
                        float* __restrict__ out) {
    __shared__ float sh_w[8];
    __shared__ float s_sc[H], s_sf[H];
    if (threadIdx.x < H) {
        int o = threadIdx.x;
        double sm  = (double)d_stats[2 * H + o];
        double sq  = (double)d_stats[3 * H + o];
        double mu  = sm / (double)N_NODES;
        double var = sq / (double)N_NODES - mu * mu;
        float rs = (float)(1.0 / sqrt(var + BN_EPS));
        float sc = __ldg(&g[o]) * rs;
        s_sc[o] = sc;
        s_sf[o] = __ldg(&beta[o]) - (float)mu * sc;
    }
    __syncthreads();
    int idx = blockIdx.x * blockDim.x + threadIdx.x;
    int n = idx >> 6, o = idx & 63;
    float p = 0.f;
    if (n < N_NODES) {
        float v = fmaxf(fmaf(d_agg2[idx], s_sc[o], s_sf[o]), 0.f);
        p = v * __ldg(&Wfc[o]);
    }
#pragma unroll
    for (int off = 16; off > 0; off >>= 1)
        p += __shfl_down_sync(0xffffffffu, p, off);
    if ((threadIdx.x & 31) == 0) sh_w[threadIdx.x >> 5] = p;
    __syncthreads();
    if (threadIdx.x < 4) {
        int nn = blockIdx.x * 4 + threadIdx.x;
        if (nn < N_NODES) {
            float t = sh_w[2 * threadIdx.x] + sh_w[2 * threadIdx.x + 1] + __ldg(bfc);
            out[nn] = 1.f / (1.f + expf(-t));
        }
    }
}

// ---------------- launch ----------------
extern "C" void kernel_launch(void* const* d_in, const int* in_sizes, int n_in,
                              void* d_out, int out_size) {
    const float* x     = (const float*)d_in[0];
    const float* ea    = (const float*)d_in[1];
    const float* We1   = (const float*)d_in[2];
    const float* be1   = (const float*)d_in[3];
    const float* root1 = (const float*)d_in[4];
    const float* b1    = (const float*)d_in[5];
    const float* g1    = (const float*)d_in[6];
    const float* beta1 = (const float*)d_in[7];
    const float* We2   = (const float*)d_in[8];
    const float* be2   = (const float*)d_in[9];
    const float* root2 = (const float*)d_in[10];
    const float* b2    = (const float*)d_in[11];
    const float* g2    = (const float*)d_in[12];
    const float* beta2 = (const float*)d_in[13];
    const float* Wfc   = (const float*)d_in[14];
    const float* bfc   = (const float*)d_in[15];
    const int*   eidx  = (const int*)d_in[16];
    float* out = (float*)d_out;

    const int NB_ELEM = (N_NODES * H + 255) / 256;   // 12500
    dim3 egrid(222, 2);   // 444 blocks = one wave at 3 blocks/SM

    // index 3 = short k_edge2 pre-pass (profiling target; output-neutral:
    // its garbage d_agg2 adds are fully overwritten by k_init_agg2 below)
    k_prep<<<32, 256>>>(We1, be1, We2, be2, root1, root2);
    k_dummy<<<1, 32>>>();
    k_dummy<<<1, 32>>>();
    k_edge2<<<egrid, 256>>>((const float4*)ea, eidx, 23680);
    k_init_agg1<<<N_NODES / 16, 256>>>(x, b1);
    k_edge1<<<444, 256>>>(x, (const float4*)ea, eidx);
    k_stats<<<296, 512>>>(0);
    k_init_agg2<<<N_NODES / 16, 256>>>(b2, g1, beta1);
    k_edge2<<<egrid, 256>>>((const float4*)ea, eidx, N_EDGES);
    k_stats<<<296, 512>>>(1);
    k_final<<<NB_ELEM, 256>>>(g2, beta2, Wfc, bfc, out);
}

// round 15
// speedup vs baseline: 1.1862x; 1.1862x over previous
#include <cuda_runtime.h>
#include <math.h>

#define N_NODES 50000
#define N_EDGES 100000
#define FN 22
#define FE 4
#define H 64
#define BN_EPS 1e-5
#define EB 16           // edges per block-batch (N_EDGES % EB == 0)

typedef unsigned long long u64;

// ---------------- packed f32x2 helpers ----------------
__device__ __forceinline__ u64 pack2(float lo, float hi) {
    u64 r; asm("mov.b64 %0, {%1, %2};" : "=l"(r) : "f"(lo), "f"(hi)); return r;
}
__device__ __forceinline__ void unpack2(u64 v, float& lo, float& hi) {
    asm("mov.b64 {%0, %1}, %2;" : "=f"(lo), "=f"(hi) : "l"(v));
}
__device__ __forceinline__ u64 fma2(u64 a, u64 b, u64 c) {
    u64 d; asm("fma.rn.f32x2 %0, %1, %2, %3;" : "=l"(d) : "l"(a), "l"(b), "l"(c)); return d;
}
__device__ __forceinline__ u64 add2(u64 a, u64 b) {
    u64 d; asm("add.rn.f32x2 %0, %1, %2;" : "=l"(d) : "l"(a), "l"(b)); return d;
}
__device__ __forceinline__ u64 relu2(u64 v) {
    float a, b; unpack2(v, a, b);
    return pack2(fmaxf(a, 0.f), fmaxf(b, 0.f));
}

// ---------------- scratch (static device globals) ----------------
__device__ float d_agg1[N_NODES * H];
__device__ float d_h1  [N_NODES * H];
__device__ float d_agg2[N_NODES * H];
__device__ u64   d_We1p[24 * 32 * 4];   // [i<24][cp<32][f<4] packed col-pairs (zero-padded i>=22)
__device__ u64   d_be1p[24 * 32];
__device__ u64   d_We2p[64 * 32 * 4];
__device__ u64   d_be2p[64 * 32];
__device__ u64   d_root1p[FN * 32];     // [i<22][cp] packed col-pairs of root1
__device__ u64   d_root2p[64 * 32];     // [i][cp]
__device__ float d_stats[4 * H];        // sum1, sq1, sum2, sq2

// ---------------- dummy (keeps ncu capture on k_edge1 at launch index 3) ----------------
__global__ void k_dummy() {}

// ---------------- prep: pack weights, zero stats ----------------
__global__ void k_prep(const float* __restrict__ We1, const float* __restrict__ be1,
                       const float* __restrict__ We2, const float* __restrict__ be2,
                       const float* __restrict__ root1, const float* __restrict__ root2) {
    int j = blockIdx.x * blockDim.x + threadIdx.x;
    if (j < 64 * 32 * 4) {
        int f = j & 3, cp = (j >> 2) & 31, i = j >> 7;
        d_We2p[j] = pack2(We2[f * 4096 + i * 64 + 2 * cp], We2[f * 4096 + i * 64 + 2 * cp + 1]);
    }
    if (j < 24 * 32 * 4) {
        int f = j & 3, cp = (j >> 2) & 31, i = j >> 7;
        d_We1p[j] = (i < FN) ? pack2(We1[f * 1408 + i * 64 + 2 * cp],
                                     We1[f * 1408 + i * 64 + 2 * cp + 1]) : 0ULL;
    }
    if (j < 64 * 32) {
        int cp = j & 31, i = j >> 5;
        d_be2p[j]   = pack2(be2[i * 64 + 2 * cp],   be2[i * 64 + 2 * cp + 1]);
        d_root2p[j] = pack2(root2[i * 64 + 2 * cp], root2[i * 64 + 2 * cp + 1]);
    }
    if (j < 24 * 32) {
        int cp = j & 31, i = j >> 5;
        d_be1p[j] = (i < FN) ? pack2(be1[i * 64 + 2 * cp], be1[i * 64 + 2 * cp + 1]) : 0ULL;
    }
    if (j < FN * 32) {
        int cp = j & 31, i = j >> 5;
        d_root1p[j] = pack2(root1[i * 64 + 2 * cp], root1[i * 64 + 2 * cp + 1]);
    }
    if (j < 4 * H) d_stats[j] = 0.f;
}

// ---------------- agg1 = x @ root1 + b1 (shared-staged, packed) ----------------
__global__ __launch_bounds__(256, 4)
void k_init_agg1(const float* __restrict__ x, const float* __restrict__ b1) {
    __shared__ u64   sh_r1[FN * 32];
    __shared__ float sh_x[16 * FN];
    const int tid = threadIdx.x;
    const int nb = blockIdx.x * 16;

    for (int t = tid; t < FN * 32; t += 256) sh_r1[t] = d_root1p[t];
    for (int t = tid; t < 16 * FN; t += 256) sh_x[t] = __ldg(&x[nb * FN + t]);
    __syncthreads();

    const int cp  = tid & 31;
    const int nl0 = (tid >> 5) * 2, nl1 = nl0 + 1;
    u64 bias = pack2(__ldg(&b1[2 * cp]), __ldg(&b1[2 * cp + 1]));
    u64 acc0 = bias, acc1 = bias;
#pragma unroll
    for (int i = 0; i < FN; i++) {
        u64 w = sh_r1[i * 32 + cp];
        float h0 = sh_x[nl0 * FN + i], h1 = sh_x[nl1 * FN + i];
        acc0 = fma2(pack2(h0, h0), w, acc0);
        acc1 = fma2(pack2(h1, h1), w, acc1);
    }
    float a, b;
    unpack2(acc0, a, b); ((float2*)&d_agg1[(nb + nl0) * H])[cp] = make_float2(a, b);
    unpack2(acc1, a, b); ((float2*)&d_agg1[(nb + nl1) * H])[cp] = make_float2(a, b);
}

// ---------------- layer-1 edge kernel: EB=16, STS partials + warp-per-edge reduce ----------
// compute: cp = tid>>3 (col pair), ig = tid&7 (i-group of 3); reduce: warp w = edges w, w+8
__global__ __launch_bounds__(256, 3)
void k_edge1(const float* __restrict__ x, const float4* __restrict__ ea4,
             const int* __restrict__ eidx) {
    const int tid = threadIdx.x;
    const int cp = tid >> 3;
    const int ig = tid & 7;
    const int wid = tid >> 5, lane = tid & 31;
    u64 W[3][4]; u64 B[3];
#pragma unroll
    for (int ii = 0; ii < 3; ii++) {
        int i = ig * 3 + ii;
#pragma unroll
        for (int f = 0; f < 4; f++) W[ii][f] = d_We1p[(i * 32 + cp) * 4 + f];
        B[ii] = d_be1p[i * 32 + cp];
    }
    __shared__ float  sh_x[2][EB][24];
    __shared__ float4 sh_ea[2][EB];
    __shared__ int    sh_dst[2][EB];
    __shared__ u64    sh_part[EB * 264];   // [k][ig] pitch-33 [cp]

    auto load = [&](int b, int buf) {
#pragma unroll
        for (int rep = 0; rep < 2; rep++) {
            int slot = wid + rep * 8;
            int e = b + slot;                    // always < N_EDGES (full batches)
            int src = __ldg(&eidx[e]);
            if (lane < 24)
                sh_x[buf][slot][lane] = (lane < FN) ? __ldg(&x[src * FN + lane]) : 0.f;
            if (lane == 0) {
                sh_ea[buf][slot]  = __ldg(&ea4[e]);
                sh_dst[buf][slot] = __ldg(&eidx[N_EDGES + e]);
            }
        }
    };

    const int step = gridDim.x * EB;
    int base = blockIdx.x * EB;
    load(base, 0);
    int buf = 0;
    for (int b = base; b < N_EDGES; b += step) {
        __syncthreads();                       // prefetch visible AND prev reduce done
        if (b + step < N_EDGES) load(b + step, buf ^ 1);
#pragma unroll 1
        for (int k = 0; k < EB; k++) {
            float4 a = sh_ea[buf][k];
            u64 ax = pack2(a.x, a.x), ay = pack2(a.y, a.y);
            u64 az = pack2(a.z, a.z), aw = pack2(a.w, a.w);
            u64 acc = 0ULL;
#pragma unroll
            for (int ii = 0; ii < 3; ii++) {
                u64 w = fma2(ax, W[ii][0], B[ii]);
                w = fma2(ay, W[ii][1], w);
                w = fma2(az, W[ii][2], w);
                w = fma2(aw, W[ii][3], w);
                w = relu2(w);
                float h = sh_x[buf][k][ig * 3 + ii];
                acc = fma2(pack2(h, h), w, acc);
            }
            sh_part[k * 264 + ig * 33 + cp] = acc;   // STS.64, no tail
        }
        __syncthreads();
#pragma unroll
        for (int rep = 0; rep < 2; rep++) {    // warp wid reduces edges wid, wid+8
            int k = wid + rep * 8;
            const u64* p = &sh_part[k * 264 + lane];
            u64 s = add2(add2(add2(p[0],   p[33]),  add2(p[66],  p[99])),
                         add2(add2(p[132], p[165]), add2(p[198], p[231])));
            float s0, s1; unpack2(s, s0, s1);
            int dst = sh_dst[buf][k];
            atomicAdd(&d_agg1[dst * H + 2 * lane],     s0);
            atomicAdd(&d_agg1[dst * H + 2 * lane + 1], s1);
        }
        buf ^= 1;
    }
}

// ---------------- BN stats (fp32, float4 loads, 512 threads) ----------------
__global__ __launch_bounds__(512)
void k_stats(int layer) {
    const float4* __restrict__ src = (const float4*)(layer ? d_agg2 : d_agg1);
    int og = threadIdx.x & 15;
    int r  = threadIdx.x >> 4;
    float4 s  = make_float4(0.f, 0.f, 0.f, 0.f);
    float4 ss = make_float4(0.f, 0.f, 0.f, 0.f);
#pragma unroll 4
    for (int n = blockIdx.x * 32 + r; n < N_NODES; n += gridDim.x * 32) {
        float4 v = src[n * 16 + og];
        s.x += v.x; s.y += v.y; s.z += v.z; s.w += v.w;
        ss.x += v.x * v.x; ss.y += v.y * v.y; ss.z += v.z * v.z; ss.w += v.w * v.w;
    }
    __shared__ float4 shs[512], shss[512];
    shs[threadIdx.x] = s; shss[threadIdx.x] = ss;
    __syncthreads();
    for (int str = 256; str >= 16; str >>= 1) {
        if (threadIdx.x < str) {
            float4 a = shs[threadIdx.x], b = shs[threadIdx.x + str];
            shs[threadIdx.x] = make_float4(a.x + b.x, a.y + b.y, a.z + b.z, a.w + b.w);
            a = shss[threadIdx.x]; b = shss[threadIdx.x + str];
            shss[threadIdx.x] = make_float4(a.x + b.x, a.y + b.y, a.z + b.z, a.w + b.w);
        }
        __syncthreads();
    }
    if (threadIdx.x < 16) {
        float4 a = shs[threadIdx.x], b = shss[threadIdx.x];
        float* ps = &d_stats[layer * 2 * H + threadIdx.x * 4];
        float* pq = &d_stats[layer * 2 * H + H + threadIdx.x * 4];
        atomicAdd(&ps[0], a.x); atomicAdd(&ps[1], a.y); atomicAdd(&ps[2], a.z); atomicAdd(&ps[3], a.w);
        atomicAdd(&pq[0], b.x); atomicAdd(&pq[1], b.y); atomicAdd(&pq[2], b.z); atomicAdd(&pq[3], b.w);
    }
}

// ---------------- fused: BN1 finalize+apply + ReLU -> h1 ; agg2 = h1 @ root2 + b2 ----------------
__global__ __launch_bounds__(256, 4)
void k_init_agg2(const float* __restrict__ b2, const float* __restrict__ g,
                 const float* __restrict__ beta) {
    __shared__ u64   sh_r2[64 * 32];
    __shared__ float sh_h[16][H];
    __shared__ float s_sc[H], s_sf[H];
    const int tid = threadIdx.x;
    const int wid = tid >> 5, lane = tid & 31;
    const int nb = blockIdx.x * 16;

    if (tid < H) {
        double sm  = (double)d_stats[tid];
        double sq  = (double)d_stats[H + tid];
        double mu  = sm / (double)N_NODES;
        double var = sq / (double)N_NODES - mu * mu;
        float rs = (float)(1.0 / sqrt(var + BN_EPS));
        float sc = __ldg(&g[tid]) * rs;
        s_sc[tid] = sc;
        s_sf[tid] = __ldg(&beta[tid]) - (float)mu * sc;
    }
    for (int t = tid; t < 64 * 32; t += 256) sh_r2[t] = d_root2p[t];
    __syncthreads();

    float2 sc = ((const float2*)s_sc)[lane];
    float2 sf = ((const float2*)s_sf)[lane];
#pragma unroll
    for (int rep = 0; rep < 2; rep++) {
        int nl = wid + rep * 8;
        int node = nb + nl;
        float2 v = ((const float2*)&d_agg1[node * H])[lane];
        v.x = fmaxf(fmaf(v.x, sc.x, sf.x), 0.f);
        v.y = fmaxf(fmaf(v.y, sc.y, sf.y), 0.f);
        ((float2*)&sh_h[nl][0])[lane] = v;
        ((float2*)&d_h1[node * H])[lane] = v;
    }
    __syncthreads();

    const int cp = tid & 31;
    const int nl0 = (tid >> 5) * 2, nl1 = nl0 + 1;
    u64 bias = pack2(__ldg(&b2[2 * cp]), __ldg(&b2[2 * cp + 1]));
    u64 acc0 = bias, acc1 = bias;
#pragma unroll
    for (int i = 0; i < H; i++) {
        u64 w2 = sh_r2[i * 32 + cp];
        float h0 = sh_h[nl0][i], h1 = sh_h[nl1][i];
        acc0 = fma2(pack2(h0, h0), w2, acc0);
        acc1 = fma2(pack2(h1, h1), w2, acc1);
    }
    float a, b;
    unpack2(acc0, a, b); ((float2*)&d_agg2[(nb + nl0) * H])[cp] = make_float2(a, b);
    unpack2(acc1, a, b); ((float2*)&d_agg2[(nb + nl1) * H])[cp] = make_float2(a, b);
}

// ---------------- layer-2 edge kernel: EB=16, STS partials + warp-per-edge reduce ----------
__global__ __launch_bounds__(256, 2)
void k_edge2(const float4* __restrict__ ea4, const int* __restrict__ eidx) {
    const int tid = threadIdx.x;
    const int cp = tid >> 3;
    const int ig = tid & 7;
    const int wid = tid >> 5, lane = tid & 31;
    u64 W[8][4]; u64 B[8];
#pragma unroll
    for (int ii = 0; ii < 8; ii++) {
        int i = ig * 8 + ii;
#pragma unroll
        for (int f = 0; f < 4; f++) W[ii][f] = d_We2p[(i * 32 + cp) * 4 + f];
        B[ii] = d_be2p[i * 32 + cp];
    }
    __shared__ float  sh_h[2][EB][H];      // 8KB
    __shared__ float4 sh_ea[2][EB];
    __shared__ int    sh_dst[2][EB];
    __shared__ u64    sh_part[EB * 264];   // 33.8KB [k][ig] pitch-33 [cp]

    auto load = [&](int b, int buf) {
#pragma unroll
        for (int rep = 0; rep < 2; rep++) {
            int slot = wid + rep * 8;
            int e = b + slot;                    // always < N_EDGES (full batches)
            int src = __ldg(&eidx[e]);
            float2 v = __ldg((const float2*)&d_h1[src * H] + lane);
            ((float2*)&sh_h[buf][slot][0])[lane] = v;
            if (lane == 0) {
                sh_ea[buf][slot]  = __ldg(&ea4[e]);
                sh_dst[buf][slot] = __ldg(&eidx[N_EDGES + e]);
            }
        }
    };

    const int step = gridDim.x * EB;
    int base = blockIdx.x * EB;
    load(base, 0);
    int buf = 0;
    for (int b = base; b < N_EDGES; b += step) {
        __syncthreads();                       // prefetch visible AND prev reduce done
        if (b + step < N_EDGES) load(b + step, buf ^ 1);
#pragma unroll 1
        for (int k = 0; k < EB; k++) {
            float4 a = sh_ea[buf][k];
            u64 ax = pack2(a.x, a.x), ay = pack2(a.y, a.y);
            u64 az = pack2(a.z, a.z), aw = pack2(a.w, a.w);
            u64 acc = 0ULL;
#pragma unroll
            for (int ii = 0; ii < 8; ii++) {
                u64 w = fma2(ax, W[ii][0], B[ii]);
                w = fma2(ay, W[ii][1], w);
                w = fma2(az, W[ii][2], w);
                w = fma2(aw, W[ii][3], w);
                w = relu2(w);
                float h = sh_h[buf][k][ig * 8 + ii];
                acc = fma2(pack2(h, h), w, acc);
            }
            sh_part[k * 264 + ig * 33 + cp] = acc;
        }
        __syncthreads();
#pragma unroll
        for (int rep = 0; rep < 2; rep++) {    // warp wid reduces edges wid, wid+8
            int k = wid + rep * 8;
            const u64* p = &sh_part[k * 264 + lane];
            u64 s = add2(add2(add2(p[0],   p[33]),  add2(p[66],  p[99])),
                         add2(add2(p[132], p[165]), add2(p[198], p[231])));
            float s0, s1; unpack2(s, s0, s1);
            int dst = sh_dst[buf][k];
            atomicAdd(&d_agg2[dst * H + 2 * lane],     s0);
            atomicAdd(&d_agg2[dst * H + 2 * lane + 1], s1);
        }
        buf ^= 1;
    }
}

// ---------------- BN2 finalize+apply + ReLU + FC + sigmoid ----------------
__global__ void k_final(const float* __restrict__ g, const float* __restrict__ beta,
                        const float* __restrict__ Wfc, const float* __restrict__ bfc,
                        float* __restrict__ out) {
    __shared__ float sh_w[8];
    __shared__ float s_sc[H], s_sf[H];
    if (threadIdx.x < H) {
        int o = threadIdx.x;
        double sm  = (double)d_stats[2 * H + o];
        double sq  = (double)d_stats[3 * H + o];
        double mu  = sm / (double)N_NODES;
        double var = sq / (double)N_NODES - mu * mu;
        float rs = (float)(1.0 / sqrt(var + BN_EPS));
        float sc = __ldg(&g[o]) * rs;
        s_sc[o] = sc;
        s_sf[o] = __ldg(&beta[o]) - (float)mu * sc;
    }
    __syncthreads();
    int idx = blockIdx.x * blockDim.x + threadIdx.x;
    int n = idx >> 6, o = idx & 63;
    float p = 0.f;
    if (n < N_NODES) {
        float v = fmaxf(fmaf(d_agg2[idx], s_sc[o], s_sf[o]), 0.f);
        p = v * __ldg(&Wfc[o]);
    }
#pragma unroll
    for (int off = 16; off > 0; off >>= 1)
        p += __shfl_down_sync(0xffffffffu, p, off);
    if ((threadIdx.x & 31) == 0) sh_w[threadIdx.x >> 5] = p;
    __syncthreads();
    if (threadIdx.x < 4) {
        int nn = blockIdx.x * 4 + threadIdx.x;
        if (nn < N_NODES) {
            float t = sh_w[2 * threadIdx.x] + sh_w[2 * threadIdx.x + 1] + __ldg(bfc);
            out[nn] = 1.f / (1.f + expf(-t));
        }
    }
}

// ---------------- launch ----------------
extern "C" void kernel_launch(void* const* d_in, const int* in_sizes, int n_in,
                              void* d_out, int out_size) {
    const float* x     = (const float*)d_in[0];
    const float* ea    = (const float*)d_in[1];
    const float* We1   = (const float*)d_in[2];
    const float* be1   = (const float*)d_in[3];
    const float* root1 = (const float*)d_in[4];
    const float* b1    = (const float*)d_in[5];
    const float* g1    = (const float*)d_in[6];
    const float* beta1 = (const float*)d_in[7];
    const float* We2   = (const float*)d_in[8];
    const float* be2   = (const float*)d_in[9];
    const float* root2 = (const float*)d_in[10];
    const float* b2    = (const float*)d_in[11];
    const float* g2    = (const float*)d_in[12];
    const float* beta2 = (const float*)d_in[13];
    const float* Wfc   = (const float*)d_in[14];
    const float* bfc   = (const float*)d_in[15];
    const int*   eidx  = (const int*)d_in[16];
    float* out = (float*)d_out;

    const int NB_ELEM = (N_NODES * H + 255) / 256;   // 12500

    // launch index 3 = k_edge1 (ncu captures the 4th launch)
    k_prep<<<32, 256>>>(We1, be1, We2, be2, root1, root2);
    k_init_agg1<<<N_NODES / 16, 256>>>(x, b1);
    k_dummy<<<1, 32>>>();
    k_edge1<<<444, 256>>>(x, (const float4*)ea, eidx);
    k_stats<<<296, 512>>>(0);
    k_init_agg2<<<N_NODES / 16, 256>>>(b2, g1, beta1);
    k_edge2<<<296, 256>>>((const float4*)ea, eidx);
    k_stats<<<296, 512>>>(1);
    k_final<<<NB_ELEM, 256>>>(g2, beta2, Wfc, bfc, out);
}

// round 16
// speedup vs baseline: 1.1960x; 1.0083x over previous
#include <cuda_runtime.h>
#include <math.h>

#define N_NODES 50000
#define N_EDGES 100000
#define FN 22
#define FE 4
#define H 64
#define BN_EPS 1e-5
#define EB 16           // edges per block-batch (N_EDGES % EB == 0)

typedef unsigned long long u64;

// ---------------- packed f32x2 helpers ----------------
__device__ __forceinline__ u64 pack2(float lo, float hi) {
    u64 r; asm("mov.b64 %0, {%1, %2};" : "=l"(r) : "f"(lo), "f"(hi)); return r;
}
__device__ __forceinline__ void unpack2(u64 v, float& lo, float& hi) {
    asm("mov.b64 {%0, %1}, %2;" : "=f"(lo), "=f"(hi) : "l"(v));
}
__device__ __forceinline__ u64 fma2(u64 a, u64 b, u64 c) {
    u64 d; asm("fma.rn.f32x2 %0, %1, %2, %3;" : "=l"(d) : "l"(a), "l"(b), "l"(c)); return d;
}
__device__ __forceinline__ u64 add2(u64 a, u64 b) {
    u64 d; asm("add.rn.f32x2 %0, %1, %2;" : "=l"(d) : "l"(a), "l"(b)); return d;
}
__device__ __forceinline__ u64 relu2(u64 v) {
    float a, b; unpack2(v, a, b);
    return pack2(fmaxf(a, 0.f), fmaxf(b, 0.f));
}
__device__ __forceinline__ void red_add_v2(float* p, float s0, float s1) {
    asm volatile("red.global.add.v2.f32 [%0], {%1, %2};" :: "l"(p), "f"(s0), "f"(s1) : "memory");
}

// ---------------- scratch (static device globals) ----------------
__device__ float d_agg1[N_NODES * H];
__device__ float d_h1  [N_NODES * H];
__device__ float d_agg2[N_NODES * H];
__device__ u64   d_We1p[24 * 32 * 4];   // [i<24][cp<32][f<4] packed col-pairs (zero-padded i>=22)
__device__ u64   d_be1p[24 * 32];
__device__ u64   d_We2p[64 * 32 * 4];
__device__ u64   d_be2p[64 * 32];
__device__ u64   d_root1p[FN * 32];     // [i<22][cp] packed col-pairs of root1
__device__ u64   d_root2p[64 * 32];     // [i][cp]
__device__ float d_stats[4 * H];        // sum1, sq1, sum2, sq2

// ---------------- dummy (keeps ncu capture on k_edge1 at launch index 3) ----------------
__global__ void k_dummy() {}

// ---------------- prep: pack weights, zero stats ----------------
__global__ void k_prep(const float* __restrict__ We1, const float* __restrict__ be1,
                       const float* __restrict__ We2, const float* __restrict__ be2,
                       const float* __restrict__ root1, const float* __restrict__ root2) {
    int j = blockIdx.x * blockDim.x + threadIdx.x;
    if (j < 64 * 32 * 4) {
        int f = j & 3, cp = (j >> 2) & 31, i = j >> 7;
        d_We2p[j] = pack2(We2[f * 4096 + i * 64 + 2 * cp], We2[f * 4096 + i * 64 + 2 * cp + 1]);
    }
    if (j < 24 * 32 * 4) {
        int f = j & 3, cp = (j >> 2) & 31, i = j >> 7;
        d_We1p[j] = (i < FN) ? pack2(We1[f * 1408 + i * 64 + 2 * cp],
                                     We1[f * 1408 + i * 64 + 2 * cp + 1]) : 0ULL;
    }
    if (j < 64 * 32) {
        int cp = j & 31, i = j >> 5;
        d_be2p[j]   = pack2(be2[i * 64 + 2 * cp],   be2[i * 64 + 2 * cp + 1]);
        d_root2p[j] = pack2(root2[i * 64 + 2 * cp], root2[i * 64 + 2 * cp + 1]);
    }
    if (j < 24 * 32) {
        int cp = j & 31, i = j >> 5;
        d_be1p[j] = (i < FN) ? pack2(be1[i * 64 + 2 * cp], be1[i * 64 + 2 * cp + 1]) : 0ULL;
    }
    if (j < FN * 32) {
        int cp = j & 31, i = j >> 5;
        d_root1p[j] = pack2(root1[i * 64 + 2 * cp], root1[i * 64 + 2 * cp + 1]);
    }
    if (j < 4 * H) d_stats[j] = 0.f;
}

// ---------------- agg1 = x @ root1 + b1 (shared-staged, packed) ----------------
__global__ __launch_bounds__(256, 4)
void k_init_agg1(const float* __restrict__ x, const float* __restrict__ b1) {
    __shared__ u64   sh_r1[FN * 32];
    __shared__ float sh_x[16 * FN];
    const int tid = threadIdx.x;
    const int nb = blockIdx.x * 16;

    for (int t = tid; t < FN * 32; t += 256) sh_r1[t] = d_root1p[t];
    for (int t = tid; t < 16 * FN; t += 256) sh_x[t] = __ldg(&x[nb * FN + t]);
    __syncthreads();

    const int cp  = tid & 31;
    const int nl0 = (tid >> 5) * 2, nl1 = nl0 + 1;
    u64 bias = pack2(__ldg(&b1[2 * cp]), __ldg(&b1[2 * cp + 1]));
    u64 acc0 = bias, acc1 = bias;
#pragma unroll
    for (int i = 0; i < FN; i++) {
        u64 w = sh_r1[i * 32 + cp];
        float h0 = sh_x[nl0 * FN + i], h1 = sh_x[nl1 * FN + i];
        acc0 = fma2(pack2(h0, h0), w, acc0);
        acc1 = fma2(pack2(h1, h1), w, acc1);
    }
    float a, b;
    unpack2(acc0, a, b); ((float2*)&d_agg1[(nb + nl0) * H])[cp] = make_float2(a, b);
    unpack2(acc1, a, b); ((float2*)&d_agg1[(nb + nl1) * H])[cp] = make_float2(a, b);
}

// ---------------- layer-1 edge kernel: EB=16, STS partials + warp-per-edge reduce ----------
// compute: cp = tid>>3 (col pair), ig = tid&7 (i-group of 3); reduce: warp w = edges w, w+8
__global__ __launch_bounds__(256, 3)
void k_edge1(const float* __restrict__ x, const float4* __restrict__ ea4,
             const int* __restrict__ eidx) {
    const int tid = threadIdx.x;
    const int cp = tid >> 3;
    const int ig = tid & 7;
    const int wid = tid >> 5, lane = tid & 31;
    u64 W[3][4]; u64 B[3];
#pragma unroll
    for (int ii = 0; ii < 3; ii++) {
        int i = ig * 3 + ii;
#pragma unroll
        for (int f = 0; f < 4; f++) W[ii][f] = d_We1p[(i * 32 + cp) * 4 + f];
        B[ii] = d_be1p[i * 32 + cp];
    }
    __shared__ float  sh_x[2][EB][24];
    __shared__ float4 sh_ea[2][EB];
    __shared__ int    sh_dst[2][EB];
    __shared__ u64    sh_part[EB * 264];   // [k][ig] pitch-33 [cp]

    auto load = [&](int b, int buf) {
#pragma unroll
        for (int rep = 0; rep < 2; rep++) {
            int slot = wid + rep * 8;
            int e = b + slot;                    // always < N_EDGES (full batches)
            int src = __ldg(&eidx[e]);
            if (lane < 24)
                sh_x[buf][slot][lane] = (lane < FN) ? __ldg(&x[src * FN + lane]) : 0.f;
            if (lane == 0) {
                sh_ea[buf][slot]  = __ldg(&ea4[e]);
                sh_dst[buf][slot] = __ldg(&eidx[N_EDGES + e]);
            }
        }
    };

    const int step = gridDim.x * EB;
    int base = blockIdx.x * EB;
    load(base, 0);
    int buf = 0;
    for (int b = base; b < N_EDGES; b += step) {
        __syncthreads();                       // prefetch visible AND prev reduce done
        if (b + step < N_EDGES) load(b + step, buf ^ 1);
#pragma unroll 1
        for (int k = 0; k < EB; k++) {
            float4 a = sh_ea[buf][k];
            u64 ax = pack2(a.x, a.x), ay = pack2(a.y, a.y);
            u64 az = pack2(a.z, a.z), aw = pack2(a.w, a.w);
            u64 acc = 0ULL;
#pragma unroll
            for (int ii = 0; ii < 3; ii++) {
                u64 w = fma2(ax, W[ii][0], B[ii]);
                w = fma2(ay, W[ii][1], w);
                w = fma2(az, W[ii][2], w);
                w = fma2(aw, W[ii][3], w);
                w = relu2(w);
                float h = sh_x[buf][k][ig * 3 + ii];
                acc = fma2(pack2(h, h), w, acc);
            }
            sh_part[k * 264 + ig * 33 + cp] = acc;   // STS.64, no tail
        }
        __syncthreads();
#pragma unroll
        for (int rep = 0; rep < 2; rep++) {    // warp wid reduces edges wid, wid+8
            int k = wid + rep * 8;
            const u64* p = &sh_part[k * 264 + lane];
            u64 s = add2(add2(add2(p[0],   p[33]),  add2(p[66],  p[99])),
                         add2(add2(p[132], p[165]), add2(p[198], p[231])));
            float s0, s1; unpack2(s, s0, s1);
            int dst = sh_dst[buf][k];
            red_add_v2(&d_agg1[dst * H + 2 * lane], s0, s1);
        }
        buf ^= 1;
    }
}

// ---------------- BN stats (fp32, float4 loads, 512 threads) ----------------
__global__ __launch_bounds__(512)
void k_stats(int layer) {
    const float4* __restrict__ src = (const float4*)(layer ? d_agg2 : d_agg1);
    int og = threadIdx.x & 15;
    int r  = threadIdx.x >> 4;
    float4 s  = make_float4(0.f, 0.f, 0.f, 0.f);
    float4 ss = make_float4(0.f, 0.f, 0.f, 0.f);
#pragma unroll 4
    for (int n = blockIdx.x * 32 + r; n < N_NODES; n += gridDim.x * 32) {
        float4 v = src[n * 16 + og];
        s.x += v.x; s.y += v.y; s.z += v.z; s.w += v.w;
        ss.x += v.x * v.x; ss.y += v.y * v.y; ss.z += v.z * v.z; ss.w += v.w * v.w;
    }
    __shared__ float4 shs[512], shss[512];
    shs[threadIdx.x] = s; shss[threadIdx.x] = ss;
    __syncthreads();
    for (int str = 256; str >= 16; str >>= 1) {
        if (threadIdx.x < str) {
            float4 a = shs[threadIdx.x], b = shs[threadIdx.x + str];
            shs[threadIdx.x] = make_float4(a.x + b.x, a.y + b.y, a.z + b.z, a.w + b.w);
            a = shss[threadIdx.x]; b = shss[threadIdx.x + str];
            shss[threadIdx.x] = make_float4(a.x + b.x, a.y + b.y, a.z + b.z, a.w + b.w);
        }
        __syncthreads();
    }
    if (threadIdx.x < 16) {
        float4 a = shs[threadIdx.x], b = shss[threadIdx.x];
        float* ps = &d_stats[layer * 2 * H + threadIdx.x * 4];
        float* pq = &d_stats[layer * 2 * H + H + threadIdx.x * 4];
        atomicAdd(&ps[0], a.x); atomicAdd(&ps[1], a.y); atomicAdd(&ps[2], a.z); atomicAdd(&ps[3], a.w);
        atomicAdd(&pq[0], b.x); atomicAdd(&pq[1], b.y); atomicAdd(&pq[2], b.z); atomicAdd(&pq[3], b.w);
    }
}

// ---------------- fused: BN1 finalize+apply + ReLU -> h1 ; agg2 = h1 @ root2 + b2 ----------------
__global__ __launch_bounds__(256, 4)
void k_init_agg2(const float* __restrict__ b2, const float* __restrict__ g,
                 const float* __restrict__ beta) {
    __shared__ u64   sh_r2[64 * 32];
    __shared__ float sh_h[16][H];
    __shared__ float s_sc[H], s_sf[H];
    const int tid = threadIdx.x;
    const int wid = tid >> 5, lane = tid & 31;
    const int nb = blockIdx.x * 16;

    if (tid < H) {
        double sm  = (double)d_stats[tid];
        double sq  = (double)d_stats[H + tid];
        double mu  = sm / (double)N_NODES;
        double var = sq / (double)N_NODES - mu * mu;
        float rs = (float)(1.0 / sqrt(var + BN_EPS));
        float sc = __ldg(&g[tid]) * rs;
        s_sc[tid] = sc;
        s_sf[tid] = __ldg(&beta[tid]) - (float)mu * sc;
    }
    for (int t = tid; t < 64 * 32; t += 256) sh_r2[t] = d_root2p[t];
    __syncthreads();

    float2 sc = ((const float2*)s_sc)[lane];
    float2 sf = ((const float2*)s_sf)[lane];
#pragma unroll
    for (int rep = 0; rep < 2; rep++) {
        int nl = wid + rep * 8;
        int node = nb + nl;
        float2 v = ((const float2*)&d_agg1[node * H])[lane];
        v.x = fmaxf(fmaf(v.x, sc.x, sf.x), 0.f);
        v.y = fmaxf(fmaf(v.y, sc.y, sf.y), 0.f);
        ((float2*)&sh_h[nl][0])[lane] = v;
        ((float2*)&d_h1[node * H])[lane] = v;
    }
    __syncthreads();

    const int cp = tid & 31;
    const int nl0 = (tid >> 5) * 2, nl1 = nl0 + 1;
    u64 bias = pack2(__ldg(&b2[2 * cp]), __ldg(&b2[2 * cp + 1]));
    u64 acc0 = bias, acc1 = bias;
#pragma unroll
    for (int i = 0; i < H; i++) {
        u64 w2 = sh_r2[i * 32 + cp];
        float h0 = sh_h[nl0][i], h1 = sh_h[nl1][i];
        acc0 = fma2(pack2(h0, h0), w2, acc0);
        acc1 = fma2(pack2(h1, h1), w2, acc1);
    }
    float a, b;
    unpack2(acc0, a, b); ((float2*)&d_agg2[(nb + nl0) * H])[cp] = make_float2(a, b);
    unpack2(acc1, a, b); ((float2*)&d_agg2[(nb + nl1) * H])[cp] = make_float2(a, b);
}

// ---------------- layer-2 edge kernel: EB=16, STS partials + warp-per-edge reduce ----------
__global__ __launch_bounds__(256, 2)
void k_edge2(const float4* __restrict__ ea4, const int* __restrict__ eidx) {
    const int tid = threadIdx.x;
    const int cp = tid >> 3;
    const int ig = tid & 7;
    const int wid = tid >> 5, lane = tid & 31;
    u64 W[8][4]; u64 B[8];
#pragma unroll
    for (int ii = 0; ii < 8; ii++) {
        int i = ig * 8 + ii;
#pragma unroll
        for (int f = 0; f < 4; f++) W[ii][f] = d_We2p[(i * 32 + cp) * 4 + f];
        B[ii] = d_be2p[i * 32 + cp];
    }
    __shared__ float  sh_h[2][EB][H];      // 8KB
    __shared__ float4 sh_ea[2][EB];
    __shared__ int    sh_dst[2][EB];
    __shared__ u64    sh_part[EB * 264];   // 33.8KB [k][ig] pitch-33 [cp]

    auto load = [&](int b, int buf) {
#pragma unroll
        for (int rep = 0; rep < 2; rep++) {
            int slot = wid + rep * 8;
            int e = b + slot;                    // always < N_EDGES (full batches)
            int src = __ldg(&eidx[e]);
            float2 v = __ldg((const float2*)&d_h1[src * H] + lane);
            ((float2*)&sh_h[buf][slot][0])[lane] = v;
            if (lane == 0) {
                sh_ea[buf][slot]  = __ldg(&ea4[e]);
                sh_dst[buf][slot] = __ldg(&eidx[N_EDGES + e]);
            }
        }
    };

    const int step = gridDim.x * EB;
    int base = blockIdx.x * EB;
    load(base, 0);
    int buf = 0;
    for (int b = base; b < N_EDGES; b += step) {
        __syncthreads();                       // prefetch visible AND prev reduce done
        if (b + step < N_EDGES) load(b + step, buf ^ 1);
#pragma unroll 1
        for (int k = 0; k < EB; k++) {
            float4 a = sh_ea[buf][k];
            u64 ax = pack2(a.x, a.x), ay = pack2(a.y, a.y);
            u64 az = pack2(a.z, a.z), aw = pack2(a.w, a.w);
            u64 acc = 0ULL;
#pragma unroll
            for (int ii = 0; ii < 8; ii++) {
                u64 w = fma2(ax, W[ii][0], B[ii]);
                w = fma2(ay, W[ii][1], w);
                w = fma2(az, W[ii][2], w);
                w = fma2(aw, W[ii][3], w);
                w = relu2(w);
                float h = sh_h[buf][k][ig * 8 + ii];
                acc = fma2(pack2(h, h), w, acc);
            }
            sh_part[k * 264 + ig * 33 + cp] = acc;
        }
        __syncthreads();
#pragma unroll
        for (int rep = 0; rep < 2; rep++) {    // warp wid reduces edges wid, wid+8
            int k = wid + rep * 8;
            const u64* p = &sh_part[k * 264 + lane];
            u64 s = add2(add2(add2(p[0],   p[33]),  add2(p[66],  p[99])),
                         add2(add2(p[132], p[165]), add2(p[198], p[231])));
            float s0, s1; unpack2(s, s0, s1);
            int dst = sh_dst[buf][k];
            red_add_v2(&d_agg2[dst * H + 2 * lane], s0, s1);
        }
        buf ^= 1;
    }
}

// ---------------- BN2 finalize+apply + ReLU + FC + sigmoid ----------------
__global__ void k_final(const float* __restrict__ g, const float* __restrict__ beta,
                        const float* __restrict__ Wfc, const float* __restrict__ bfc,
                        float* __restrict__ out) {
    __shared__ float sh_w[8];
    __shared__ float s_sc[H], s_sf[H];
    if (threadIdx.x < H) {
        int o = threadIdx.x;
        double sm  = (double)d_stats[2 * H + o];
        double sq  = (double)d_stats[3 * H + o];
        double mu  = sm / (double)N_NODES;
        double var = sq / (double)N_NODES - mu * mu;
        float rs = (float)(1.0 / sqrt(var + BN_EPS));
        float sc = __ldg(&g[o]) * rs;
        s_sc[o] = sc;
        s_sf[o] = __ldg(&beta[o]) - (float)mu * sc;
    }
    __syncthreads();
    int idx = blockIdx.x * blockDim.x + threadIdx.x;
    int n = idx >> 6, o = idx & 63;
    float p = 0.f;
    if (n < N_NODES) {
        float v = fmaxf(fmaf(d_agg2[idx], s_sc[o], s_sf[o]), 0.f);
        p = v * __ldg(&Wfc[o]);
    }
#pragma unroll
    for (int off = 16; off > 0; off >>= 1)
        p += __shfl_down_sync(0xffffffffu, p, off);
    if ((threadIdx.x & 31) == 0) sh_w[threadIdx.x >> 5] = p;
    __syncthreads();
    if (threadIdx.x < 4) {
        int nn = blockIdx.x * 4 + threadIdx.x;
        if (nn < N_NODES) {
            float t = sh_w[2 * threadIdx.x] + sh_w[2 * threadIdx.x + 1] + __ldg(bfc);
            out[nn] = 1.f / (1.f + expf(-t));
        }
    }
}

// ---------------- launch ----------------
extern "C" void kernel_launch(void* const* d_in, const int* in_sizes, int n_in,
                              void* d_out, int out_size) {
    const float* x     = (const float*)d_in[0];
    const float* ea    = (const float*)d_in[1];
    const float* We1   = (const float*)d_in[2];
    const float* be1   = (const float*)d_in[3];
    const float* root1 = (const float*)d_in[4];
    const float* b1    = (const float*)d_in[5];
    const float* g1    = (const float*)d_in[6];
    const float* beta1 = (const float*)d_in[7];
    const float* We2   = (const float*)d_in[8];
    const float* be2   = (const float*)d_in[9];
    const float* root2 = (const float*)d_in[10];
    const float* b2    = (const float*)d_in[11];
    const float* g2    = (const float*)d_in[12];
    const float* beta2 = (const float*)d_in[13];
    const float* Wfc   = (const float*)d_in[14];
    const float* bfc   = (const float*)d_in[15];
    const int*   eidx  = (const int*)d_in[16];
    float* out = (float*)d_out;

    const int NB_ELEM = (N_NODES * H + 255) / 256;   // 12500

    // launch index 3 = k_edge1 (ncu captures the 4th launch)
    k_prep<<<32, 256>>>(We1, be1, We2, be2, root1, root2);
    k_init_agg1<<<N_NODES / 16, 256>>>(x, b1);
    k_dummy<<<1, 32>>>();
    k_edge1<<<444, 256>>>(x, (const float4*)ea, eidx);
    k_stats<<<296, 512>>>(0);
    k_init_agg2<<<N_NODES / 16, 256>>>(b2, g1, beta1);
    k_edge2<<<296, 256>>>((const float4*)ea, eidx);
    k_stats<<<296, 512>>>(1);
    k_final<<<NB_ELEM, 256>>>(g2, beta2, Wfc, bfc, out);
}